// round 4
// baseline (speedup 1.0000x reference)
#include <cuda_runtime.h>

#define NB   16
#define HH   56
#define HW   3136
#define DIMC 256
#define NQKV 192
#define NMID 64
#define SCALE_F 0.17677669529663688f

typedef unsigned long long u64t;

// packed f32x2 helpers (SASS FFMA2 — only reachable via PTX fma.rn.f32x2)
__device__ __forceinline__ u64t pk2(float lo, float hi) {
    u64t r; asm("mov.b64 %0, {%1, %2};" : "=l"(r) : "f"(lo), "f"(hi)); return r;
}
__device__ __forceinline__ float2 upk2(u64t v) {
    float2 f; asm("mov.b64 {%0, %1}, %2;" : "=f"(f.x), "=f"(f.y) : "l"(v)); return f;
}
__device__ __forceinline__ void ffma2(u64t& d, u64t a, u64t b) {
    asm("fma.rn.f32x2 %0, %1, %2, %0;" : "+l"(d) : "l"(a), "l"(b));
}

// Scratch (static __device__ arrays — allocation-free per harness rules)
static __device__ float g_f[NB * HW * NQKV];    // [b][pixel][192] pixel-major
static __device__ float g_mid[NB * HW * NMID];  // [b][pixel][64]  pixel-major
static __device__ float g_wT[DIMC * NQKV];      // qkv_w transposed [k][n]
static __device__ float g_pT[NMID * DIMC];      // proj_w transposed [k][n]

// ---------------------------------------------------------------------------
// Kernel 0: transpose weights once (tiny)
// ---------------------------------------------------------------------------
__global__ void k_prep(const float* __restrict__ qkv_w,
                       const float* __restrict__ proj_w) {
    int stride = gridDim.x * blockDim.x;
    int i0 = blockIdx.x * blockDim.x + threadIdx.x;
    for (int i = i0; i < DIMC * NQKV; i += stride) {
        int k = i / NQKV, n = i - k * NQKV;
        g_wT[i] = qkv_w[n * DIMC + k];
    }
    for (int i = i0; i < NMID * DIMC; i += stride) {
        int k = i / DIMC, n = i - k * DIMC;
        g_pT[i] = proj_w[n * NMID + k];
    }
}

// ---------------------------------------------------------------------------
// Kernel 1: QKV GEMM.  C[p][n] = sum_k x[b][k][p] * qkv_w[n][k] + qkv_b[n]
// Tile: 64 pixels x 192 outputs, BK=16.  256 threads.
// Thread owns 4 M-PAIRS (rows 16i+2*tm, +1) x 6 N cols; packed f32x2 FMAs.
// ---------------------------------------------------------------------------
__global__ __launch_bounds__(256) void k_qkv(const float* __restrict__ x,
                                             const float* __restrict__ qkv_b) {
    __shared__ __align__(16) float As[16 * 64];
    __shared__ float Bs[16 * 192];
    const int tid = threadIdx.x;
    const int b   = blockIdx.y;
    const int p0  = blockIdx.x * 64;
    const int tn  = tid & 31;   // n lane
    const int tm  = tid >> 5;   // m group (uniform per warp)

    u64t acc[4][6];
#pragma unroll
    for (int i = 0; i < 4; i++)
#pragma unroll
        for (int j = 0; j < 6; j++) acc[i][j] = 0ull;

    const float* xb = x + (size_t)b * DIMC * HW;

    for (int k0 = 0; k0 < DIMC; k0 += 16) {
#pragma unroll
        for (int r = 0; r < 4; r++) {
            int idx = tid + 256 * r;
            int kk = idx >> 6, m = idx & 63;
            As[kk * 64 + m] = xb[(size_t)(k0 + kk) * HW + p0 + m];
        }
#pragma unroll
        for (int r = 0; r < 12; r++) {
            int idx = tid + 256 * r;
            int kk = idx / 192, n = idx - kk * 192;
            Bs[kk * 192 + n] = g_wT[(k0 + kk) * NQKV + n];
        }
        __syncthreads();
#pragma unroll
        for (int kk = 0; kk < 16; kk++) {
            const u64t* Ap = (const u64t*)(As + kk * 64);
            u64t a2[4], b2[6];
#pragma unroll
            for (int i = 0; i < 4; i++) a2[i] = Ap[8 * i + tm];
#pragma unroll
            for (int j = 0; j < 6; j++) {
                float bv = Bs[kk * 192 + tn + 32 * j];
                b2[j] = pk2(bv, bv);
            }
#pragma unroll
            for (int i = 0; i < 4; i++)
#pragma unroll
                for (int j = 0; j < 6; j++) ffma2(acc[i][j], a2[i], b2[j]);
        }
        __syncthreads();
    }

#pragma unroll
    for (int j = 0; j < 6; j++) {
        int n = tn + 32 * j;
        float bias = qkv_b[n];
#pragma unroll
        for (int i = 0; i < 4; i++) {
            float2 v = upk2(acc[i][j]);
            size_t row = (size_t)b * HW + p0 + 16 * i + 2 * tm;
            g_f[row * NQKV + n]          = v.x + bias;
            g_f[(row + 1) * NQKV + n]    = v.y + bias;
        }
    }
}

// ---------------------------------------------------------------------------
// Kernel 2: slide attention, channel-paired with packed f32x2 FMAs.
// One thread per (pixel, head); block = 56x4 strip for one (b,h).
// k/v neighborhoods stored as float2 channel-pairs; wp & bias pre-packed.
// ---------------------------------------------------------------------------
__global__ __launch_bounds__(224) void k_attn(const float* __restrict__ dc_b,
                                              const float* __restrict__ dc1_w,
                                              const float* __restrict__ dc1_b,
                                              const float* __restrict__ rpb) {
    __shared__ float2 skp[4][6][58];
    __shared__ float2 svp[4][6][58];
    __shared__ float2 wpp[4][81];   // [cpair][idx*9+t]
    __shared__ float2 biasp[4][9];
    __shared__ float  srpb[9];

    const int tid  = threadIdx.x;
    const int tile = blockIdx.x;   // 0..13  (rows y0..y0+3)
    const int h    = blockIdx.y;
    const int b    = blockIdx.z;
    const int y0   = tile * 4;

    for (int i = tid; i < 324; i += 224) {
        int cp = i / 81, r = i - cp * 81;
        int idx = r / 9, t = r - idx * 9;
        int o0 = (2 * cp) * 9 + idx, o1 = o0 + 9;
        float id = (t == idx) ? 1.0f : 0.0f;
        wpp[cp][r] = make_float2(dc1_w[o0 * 9 + t] + id, dc1_w[o1 * 9 + t] + id);
    }
    for (int i = tid; i < 36; i += 224) {
        int cp = i / 9, idx = i - cp * 9;
        int o0 = (2 * cp) * 9 + idx, o1 = o0 + 9;
        biasp[cp][idx] = make_float2(dc_b[o0] + dc1_b[o0], dc_b[o1] + dc1_b[o1]);
    }
    if (tid < 9) srpb[tid] = rpb[h * 9 + tid];

    const float* fb = g_f + (size_t)b * HW * NQKV + h * 24;

    // halo tile: 6 rows x 58 cols, zero padded outside image
    for (int i = tid; i < 348; i += 224) {
        int hy = i / 58, hx = i - hy * 58;
        int gy = y0 + hy - 1, gx = hx - 1;
        float4 a0, a1, c0, c1;
        if (gy >= 0 && gy < HH && gx >= 0 && gx < HH) {
            const float* pf = fb + (size_t)(gy * HH + gx) * NQKV;
            a0 = *(const float4*)(pf + 8);
            a1 = *(const float4*)(pf + 12);
            c0 = *(const float4*)(pf + 16);
            c1 = *(const float4*)(pf + 20);
        } else {
            a0 = a1 = c0 = c1 = make_float4(0.f, 0.f, 0.f, 0.f);
        }
        skp[0][hy][hx] = make_float2(a0.x, a0.y);
        skp[1][hy][hx] = make_float2(a0.z, a0.w);
        skp[2][hy][hx] = make_float2(a1.x, a1.y);
        skp[3][hy][hx] = make_float2(a1.z, a1.w);
        svp[0][hy][hx] = make_float2(c0.x, c0.y);
        svp[1][hy][hx] = make_float2(c0.z, c0.w);
        svp[2][hy][hx] = make_float2(c1.x, c1.y);
        svp[3][hy][hx] = make_float2(c1.z, c1.w);
    }
    __syncthreads();

    const int ty = tid / 56, tx = tid - ty * 56;
    const int p  = (y0 + ty) * HH + tx;
    const float* pf = fb + (size_t)p * NQKV;
    float4 q0 = *(const float4*)pf;
    float4 q1 = *(const float4*)(pf + 4);
    float q[8] = {q0.x * SCALE_F, q0.y * SCALE_F, q0.z * SCALE_F, q0.w * SCALE_F,
                  q1.x * SCALE_F, q1.y * SCALE_F, q1.z * SCALE_F, q1.w * SCALE_F};
    float qsum = 0.f;
#pragma unroll
    for (int c = 0; c < 8; c++) qsum += q[c];

    float logit[9];
#pragma unroll
    for (int i = 0; i < 9; i++) logit[i] = 0.f;

    // ---- K branch: accumulate logits (channel pairs) ----
#pragma unroll
    for (int cp = 0; cp < 4; cp++) {
        u64t nb2[9];
#pragma unroll
        for (int dy = 0; dy < 3; dy++)
#pragma unroll
            for (int dx = 0; dx < 3; dx++)
                nb2[dy * 3 + dx] = *(const u64t*)&skp[cp][ty + dy][tx + dx];
        const u64t* wp2 = (const u64t*)wpp[cp];
        const u64t* bp2 = (const u64t*)biasp[cp];
        float qx = q[2 * cp], qy = q[2 * cp + 1];
#pragma unroll
        for (int idx = 0; idx < 9; idx++) {
            u64t kv = bp2[idx];
#pragma unroll
            for (int t = 0; t < 9; t++) ffma2(kv, nb2[t], wp2[idx * 9 + t]);
            float2 k2 = upk2(kv);
            logit[idx] = fmaf(qx, k2.x, fmaf(qy, k2.y, logit[idx]));
        }
    }
#pragma unroll
    for (int idx = 0; idx < 9; idx++) logit[idx] += qsum * srpb[idx];

    // ---- softmax over 9 taps ----
    float mx = logit[0];
#pragma unroll
    for (int idx = 1; idx < 9; idx++) mx = fmaxf(mx, logit[idx]);
    float s = 0.f;
    float attn[9];
#pragma unroll
    for (int idx = 0; idx < 9; idx++) {
        attn[idx] = __expf(logit[idx] - mx);
        s += attn[idx];
    }
    float inv = 1.0f / s;
    u64t attn2[9];
#pragma unroll
    for (int idx = 0; idx < 9; idx++) {
        float a = attn[idx] * inv;
        attn2[idx] = pk2(a, a);
    }

    // ---- V branch: weighted sum (channel pairs) ----
    u64t ov2[4];
#pragma unroll
    for (int cp = 0; cp < 4; cp++) ov2[cp] = 0ull;
#pragma unroll
    for (int cp = 0; cp < 4; cp++) {
        u64t nb2[9];
#pragma unroll
        for (int dy = 0; dy < 3; dy++)
#pragma unroll
            for (int dx = 0; dx < 3; dx++)
                nb2[dy * 3 + dx] = *(const u64t*)&svp[cp][ty + dy][tx + dx];
        const u64t* wp2 = (const u64t*)wpp[cp];
        const u64t* bp2 = (const u64t*)biasp[cp];
#pragma unroll
        for (int idx = 0; idx < 9; idx++) {
            u64t vv = bp2[idx];
#pragma unroll
            for (int t = 0; t < 9; t++) ffma2(vv, nb2[t], wp2[idx * 9 + t]);
            ffma2(ov2[cp], vv, attn2[idx]);
        }
    }

    float2 o0 = upk2(ov2[0]), o1 = upk2(ov2[1]);
    float2 o2 = upk2(ov2[2]), o3 = upk2(ov2[3]);
    float* po = g_mid + ((size_t)b * HW + p) * NMID + h * 8;
    *(float4*)po       = make_float4(o0.x, o0.y, o1.x, o1.y);
    *(float4*)(po + 4) = make_float4(o2.x, o2.y, o3.x, o3.y);
}

// ---------------------------------------------------------------------------
// Kernel 3: proj GEMM.  out[b][n][p] = sum_k mid[b][p][k]*proj_w[n][k]+proj_b[n]
// Tile: 64 pixels x 256 outputs, BK=16.  256 threads.
// Thread owns 4 M-pairs x 8 N cols; packed f32x2 FMAs.
// Epilogue transposes through padded smem for coalesced NCHW writes.
// ---------------------------------------------------------------------------
__global__ __launch_bounds__(256) void k_proj(const float* __restrict__ proj_b,
                                              float* __restrict__ out) {
    __shared__ __align__(16) float sbuf[128 * 65];  // 33.3KB; unions everything
    float* As = sbuf;                 // mainloop: pitch 66 (even, 8B-pair safe)
    float* Bs = sbuf + 16 * 66;       // 16 x 256
    const int tid = threadIdx.x;
    const int b   = blockIdx.y;
    const int p0  = blockIdx.x * 64;
    const int tn  = tid & 31;
    const int tm  = tid >> 5;

    u64t acc[4][8];
#pragma unroll
    for (int i = 0; i < 4; i++)
#pragma unroll
        for (int j = 0; j < 8; j++) acc[i][j] = 0ull;

    const float* midb = g_mid + (size_t)b * HW * NMID;

    for (int k0 = 0; k0 < NMID; k0 += 16) {
        {
            int m = tid >> 2, kq = (tid & 3) * 4;
            float4 v = *(const float4*)(midb + (size_t)(p0 + m) * NMID + k0 + kq);
            As[(kq + 0) * 66 + m] = v.x;
            As[(kq + 1) * 66 + m] = v.y;
            As[(kq + 2) * 66 + m] = v.z;
            As[(kq + 3) * 66 + m] = v.w;
        }
#pragma unroll
        for (int r = 0; r < 16; r++) {
            int idx = tid + 256 * r;
            int kk = idx >> 8, n = idx & 255;
            Bs[kk * 256 + n] = g_pT[(k0 + kk) * DIMC + n];
        }
        __syncthreads();
#pragma unroll
        for (int kk = 0; kk < 16; kk++) {
            const u64t* Ap = (const u64t*)(As + kk * 66);
            u64t a2[4], b2[8];
#pragma unroll
            for (int i = 0; i < 4; i++) a2[i] = Ap[8 * i + tm];
#pragma unroll
            for (int j = 0; j < 8; j++) {
                float bv = Bs[kk * 256 + tn + 32 * j];
                b2[j] = pk2(bv, bv);
            }
#pragma unroll
            for (int i = 0; i < 4; i++)
#pragma unroll
                for (int j = 0; j < 8; j++) ffma2(acc[i][j], a2[i], b2[j]);
        }
        __syncthreads();
    }

    // epilogue in two 128-channel halves through padded smem (pitch 65)
    for (int half = 0; half < 2; half++) {
        __syncthreads();
#pragma unroll
        for (int jj = 0; jj < 4; jj++) {
            int j = half * 4 + jj;
            int n = tn + 32 * j;
            float bias = proj_b[n];
            int row = n - half * 128;
#pragma unroll
            for (int i = 0; i < 4; i++) {
                float2 v = upk2(acc[i][j]);
                int m = 16 * i + 2 * tm;
                sbuf[row * 65 + m]     = v.x + bias;
                sbuf[row * 65 + m + 1] = v.y + bias;
            }
        }
        __syncthreads();
#pragma unroll
        for (int r = 0; r < 32; r++) {
            int idx = tid + 256 * r;
            int n = idx >> 6, m = idx & 63;
            out[((size_t)b * DIMC + half * 128 + n) * HW + p0 + m] = sbuf[n * 65 + m];
        }
    }
}

// ---------------------------------------------------------------------------
extern "C" void kernel_launch(void* const* d_in, const int* in_sizes, int n_in,
                              void* d_out, int out_size) {
    const float* x      = (const float*)d_in[0];
    const float* qkv_w  = (const float*)d_in[1];
    const float* qkv_b  = (const float*)d_in[2];
    const float* dc_b   = (const float*)d_in[3];
    const float* dc1_w  = (const float*)d_in[4];
    const float* dc1_b  = (const float*)d_in[5];
    const float* rpb    = (const float*)d_in[6];
    const float* proj_w = (const float*)d_in[7];
    const float* proj_b = (const float*)d_in[8];
    float* out = (float*)d_out;

    k_prep<<<64, 256>>>(qkv_w, proj_w);
    k_qkv<<<dim3(49, NB), 256>>>(x, qkv_b);
    k_attn<<<dim3(14, 8, NB), 224>>>(dc_b, dc1_w, dc1_b, rpb);
    k_proj<<<dim3(49, NB), 256>>>(proj_b, out);
    (void)in_sizes; (void)n_in; (void)out_size;
}

// round 8
// speedup vs baseline: 3.6976x; 3.6976x over previous
#include <cuda_runtime.h>

#define NB   16
#define HH   56
#define HW   3136
#define DIMC 256
#define NQKV 192
#define NMID 64
#define SCALE_F 0.17677669529663688f

typedef unsigned long long u64t;

// packed f32x2 helpers (SASS FFMA2 — only reachable via PTX fma.rn.f32x2)
__device__ __forceinline__ u64t pk2(float lo, float hi) {
    u64t r; asm("mov.b64 %0, {%1, %2};" : "=l"(r) : "f"(lo), "f"(hi)); return r;
}
__device__ __forceinline__ float2 upk2(u64t v) {
    float2 f; asm("mov.b64 {%0, %1}, %2;" : "=f"(f.x), "=f"(f.y) : "l"(v)); return f;
}
__device__ __forceinline__ void ffma2(u64t& d, u64t a, u64t b) {
    asm("fma.rn.f32x2 %0, %1, %2, %0;" : "+l"(d) : "l"(a), "l"(b));
}

// Scratch (static __device__ arrays — allocation-free per harness rules)
static __device__ float g_f[NB * HW * NQKV];        // [b][pixel][192] pixel-major
static __device__ float g_mid[NB * HW * NMID];      // [b][pixel][64]  pixel-major
static __device__ float g_attn[NB * 8 * 9 * HW];    // [b][h][idx][pixel] plane-major
static __device__ float g_wT[DIMC * NQKV];          // qkv_w transposed [k][n]
static __device__ float g_pT[NMID * DIMC];          // proj_w transposed [k][n]

// ---------------------------------------------------------------------------
// Kernel 0: transpose weights once (tiny)
// ---------------------------------------------------------------------------
__global__ void k_prep(const float* __restrict__ qkv_w,
                       const float* __restrict__ proj_w) {
    int stride = gridDim.x * blockDim.x;
    int i0 = blockIdx.x * blockDim.x + threadIdx.x;
    for (int i = i0; i < DIMC * NQKV; i += stride) {
        int k = i / NQKV, n = i - k * NQKV;
        g_wT[i] = qkv_w[n * DIMC + k];
    }
    for (int i = i0; i < NMID * DIMC; i += stride) {
        int k = i / DIMC, n = i - k * DIMC;
        g_pT[i] = proj_w[n * NMID + k];
    }
}

// ---------------------------------------------------------------------------
// Kernel 1: QKV GEMM.  C[p][n] = sum_k x[b][k][p] * qkv_w[n][k] + qkv_b[n]
// Tile: 64 pixels x 192 outputs, BK=16.  256 threads, f32x2 packed FMAs.
// ---------------------------------------------------------------------------
__global__ __launch_bounds__(256) void k_qkv(const float* __restrict__ x,
                                             const float* __restrict__ qkv_b) {
    __shared__ __align__(16) float As[16 * 64];
    __shared__ float Bs[16 * 192];
    const int tid = threadIdx.x;
    const int b   = blockIdx.y;
    const int p0  = blockIdx.x * 64;
    const int tn  = tid & 31;   // n lane
    const int tm  = tid >> 5;   // m group (uniform per warp)

    u64t acc[4][6];
#pragma unroll
    for (int i = 0; i < 4; i++)
#pragma unroll
        for (int j = 0; j < 6; j++) acc[i][j] = 0ull;

    const float* xb = x + (size_t)b * DIMC * HW;

    for (int k0 = 0; k0 < DIMC; k0 += 16) {
#pragma unroll
        for (int r = 0; r < 4; r++) {
            int idx = tid + 256 * r;
            int kk = idx >> 6, m = idx & 63;
            As[kk * 64 + m] = xb[(size_t)(k0 + kk) * HW + p0 + m];
        }
#pragma unroll
        for (int r = 0; r < 12; r++) {
            int idx = tid + 256 * r;
            int kk = idx / 192, n = idx - kk * 192;
            Bs[kk * 192 + n] = g_wT[(k0 + kk) * NQKV + n];
        }
        __syncthreads();
#pragma unroll
        for (int kk = 0; kk < 16; kk++) {
            const u64t* Ap = (const u64t*)(As + kk * 64);
            u64t a2[4], b2[6];
#pragma unroll
            for (int i = 0; i < 4; i++) a2[i] = Ap[8 * i + tm];
#pragma unroll
            for (int j = 0; j < 6; j++) {
                float bv = Bs[kk * 192 + tn + 32 * j];
                b2[j] = pk2(bv, bv);
            }
#pragma unroll
            for (int i = 0; i < 4; i++)
#pragma unroll
                for (int j = 0; j < 6; j++) ffma2(acc[i][j], a2[i], b2[j]);
        }
        __syncthreads();
    }

#pragma unroll
    for (int j = 0; j < 6; j++) {
        int n = tn + 32 * j;
        float bias = qkv_b[n];
#pragma unroll
        for (int i = 0; i < 4; i++) {
            float2 v = upk2(acc[i][j]);
            size_t row = (size_t)b * HW + p0 + 16 * i + 2 * tm;
            g_f[row * NQKV + n]       = v.x + bias;
            g_f[(row + 1) * NQKV + n] = v.y + bias;
        }
    }
}

// ---------------------------------------------------------------------------
// Kernel 2a: K branch + softmax.  Writes normalized attn weights, plane-major.
// One thread per (pixel, head); block = 56x4 strip for one (b,h).
// Scalar FFMA; launch_bounds (224,4) -> 73-reg cap, no spill risk, 28 warps/SM.
// ---------------------------------------------------------------------------
__global__ __launch_bounds__(224, 4) void k_attn_a(const float* __restrict__ dc_b,
                                                   const float* __restrict__ dc1_w,
                                                   const float* __restrict__ dc1_b,
                                                   const float* __restrict__ rpb) {
    __shared__ float sk[8][6][58];
    __shared__ float wp[72][9];
    __shared__ float sbias[72];
    __shared__ float srpb[9];

    const int tid  = threadIdx.x;
    const int tile = blockIdx.x;   // 0..13  (rows y0..y0+3)
    const int h    = blockIdx.y;
    const int b    = blockIdx.z;
    const int y0   = tile * 4;

    for (int i = tid; i < 648; i += 224) {
        int o = i / 9, t = i - o * 9;
        wp[o][t] = dc1_w[i] + ((t == (o % 9)) ? 1.0f : 0.0f);
    }
    for (int i = tid; i < 72; i += 224) sbias[i] = dc_b[i] + dc1_b[i];
    if (tid < 9) srpb[tid] = rpb[h * 9 + tid];

    const float* fb = g_f + (size_t)b * HW * NQKV + h * 24;

    // halo tile (K channels only): 6 rows x 58 cols, zero padded
    for (int i = tid; i < 348; i += 224) {
        int hy = i / 58, hx = i - hy * 58;
        int gy = y0 + hy - 1, gx = hx - 1;
        float4 a0, a1;
        if (gy >= 0 && gy < HH && gx >= 0 && gx < HH) {
            const float* pf = fb + (size_t)(gy * HH + gx) * NQKV;
            a0 = *(const float4*)(pf + 8);
            a1 = *(const float4*)(pf + 12);
        } else {
            a0 = a1 = make_float4(0.f, 0.f, 0.f, 0.f);
        }
        sk[0][hy][hx] = a0.x; sk[1][hy][hx] = a0.y;
        sk[2][hy][hx] = a0.z; sk[3][hy][hx] = a0.w;
        sk[4][hy][hx] = a1.x; sk[5][hy][hx] = a1.y;
        sk[6][hy][hx] = a1.z; sk[7][hy][hx] = a1.w;
    }
    __syncthreads();

    const int ty = tid / 56, tx = tid - ty * 56;
    const int p  = (y0 + ty) * HH + tx;
    const float* pf = fb + (size_t)p * NQKV;
    float4 q0 = *(const float4*)pf;
    float4 q1 = *(const float4*)(pf + 4);
    float q[8] = {q0.x * SCALE_F, q0.y * SCALE_F, q0.z * SCALE_F, q0.w * SCALE_F,
                  q1.x * SCALE_F, q1.y * SCALE_F, q1.z * SCALE_F, q1.w * SCALE_F};
    float qsum = 0.f;
#pragma unroll
    for (int c = 0; c < 8; c++) qsum += q[c];

    float logit[9];
#pragma unroll
    for (int i = 0; i < 9; i++) logit[i] = 0.f;

#pragma unroll
    for (int c = 0; c < 8; c++) {
        float nb[9];
#pragma unroll
        for (int dy = 0; dy < 3; dy++)
#pragma unroll
            for (int dx = 0; dx < 3; dx++)
                nb[dy * 3 + dx] = sk[c][ty + dy][tx + dx];
        float qc = q[c];
#pragma unroll
        for (int idx = 0; idx < 9; idx++) {
            int o = c * 9 + idx;
            float kv = sbias[o];
#pragma unroll
            for (int t = 0; t < 9; t++) kv = fmaf(nb[t], wp[o][t], kv);
            logit[idx] = fmaf(qc, kv, logit[idx]);
        }
    }
#pragma unroll
    for (int idx = 0; idx < 9; idx++) logit[idx] = fmaf(qsum, srpb[idx], logit[idx]);

    // softmax over 9 taps
    float mx = logit[0];
#pragma unroll
    for (int idx = 1; idx < 9; idx++) mx = fmaxf(mx, logit[idx]);
    float s = 0.f;
#pragma unroll
    for (int idx = 0; idx < 9; idx++) {
        logit[idx] = __expf(logit[idx] - mx);
        s += logit[idx];
    }
    float inv = 1.0f / s;

    float* pa = g_attn + (((size_t)b * 8 + h) * 9) * HW + p;
#pragma unroll
    for (int idx = 0; idx < 9; idx++)
        pa[(size_t)idx * HW] = logit[idx] * inv;     // coalesced per idx-plane
}

// ---------------------------------------------------------------------------
// Kernel 2b: V branch.  Reads attn planes, computes weighted sum -> g_mid.
// ---------------------------------------------------------------------------
__global__ __launch_bounds__(224, 4) void k_attn_b(const float* __restrict__ dc_b,
                                                   const float* __restrict__ dc1_w,
                                                   const float* __restrict__ dc1_b) {
    __shared__ float sv[8][6][58];
    __shared__ float wp[72][9];
    __shared__ float sbias[72];

    const int tid  = threadIdx.x;
    const int tile = blockIdx.x;
    const int h    = blockIdx.y;
    const int b    = blockIdx.z;
    const int y0   = tile * 4;

    for (int i = tid; i < 648; i += 224) {
        int o = i / 9, t = i - o * 9;
        wp[o][t] = dc1_w[i] + ((t == (o % 9)) ? 1.0f : 0.0f);
    }
    for (int i = tid; i < 72; i += 224) sbias[i] = dc_b[i] + dc1_b[i];

    const float* fb = g_f + (size_t)b * HW * NQKV + h * 24;

    // halo tile (V channels only)
    for (int i = tid; i < 348; i += 224) {
        int hy = i / 58, hx = i - hy * 58;
        int gy = y0 + hy - 1, gx = hx - 1;
        float4 c0, c1;
        if (gy >= 0 && gy < HH && gx >= 0 && gx < HH) {
            const float* pf = fb + (size_t)(gy * HH + gx) * NQKV;
            c0 = *(const float4*)(pf + 16);
            c1 = *(const float4*)(pf + 20);
        } else {
            c0 = c1 = make_float4(0.f, 0.f, 0.f, 0.f);
        }
        sv[0][hy][hx] = c0.x; sv[1][hy][hx] = c0.y;
        sv[2][hy][hx] = c0.z; sv[3][hy][hx] = c0.w;
        sv[4][hy][hx] = c1.x; sv[5][hy][hx] = c1.y;
        sv[6][hy][hx] = c1.z; sv[7][hy][hx] = c1.w;
    }
    __syncthreads();

    const int ty = tid / 56, tx = tid - ty * 56;
    const int p  = (y0 + ty) * HH + tx;

    float attn[9];
    const float* pa = g_attn + (((size_t)b * 8 + h) * 9) * HW + p;
#pragma unroll
    for (int idx = 0; idx < 9; idx++) attn[idx] = pa[(size_t)idx * HW];

    float ov[8];
#pragma unroll
    for (int c = 0; c < 8; c++) {
        float nb[9];
#pragma unroll
        for (int dy = 0; dy < 3; dy++)
#pragma unroll
            for (int dx = 0; dx < 3; dx++)
                nb[dy * 3 + dx] = sv[c][ty + dy][tx + dx];
        float oc = 0.f;
#pragma unroll
        for (int idx = 0; idx < 9; idx++) {
            int o = c * 9 + idx;
            float vv = sbias[o];
#pragma unroll
            for (int t = 0; t < 9; t++) vv = fmaf(nb[t], wp[o][t], vv);
            oc = fmaf(attn[idx], vv, oc);
        }
        ov[c] = oc;
    }

    float* po = g_mid + ((size_t)b * HW + p) * NMID + h * 8;
    *(float4*)po       = make_float4(ov[0], ov[1], ov[2], ov[3]);
    *(float4*)(po + 4) = make_float4(ov[4], ov[5], ov[6], ov[7]);
}

// ---------------------------------------------------------------------------
// Kernel 3: proj GEMM.  out[b][n][p] = sum_k mid[b][p][k]*proj_w[n][k]+proj_b[n]
// Tile: 64 pixels x 256 outputs, BK=16.  256 threads, f32x2 packed FMAs.
// Epilogue transposes through padded smem for coalesced NCHW writes.
// ---------------------------------------------------------------------------
__global__ __launch_bounds__(256) void k_proj(const float* __restrict__ proj_b,
                                              float* __restrict__ out) {
    __shared__ __align__(16) float sbuf[128 * 65];  // unions mainloop + epilogue
    float* As = sbuf;                 // mainloop: pitch 66 (even, 8B-pair safe)
    float* Bs = sbuf + 16 * 66;       // 16 x 256
    const int tid = threadIdx.x;
    const int b   = blockIdx.y;
    const int p0  = blockIdx.x * 64;
    const int tn  = tid & 31;
    const int tm  = tid >> 5;

    u64t acc[4][8];
#pragma unroll
    for (int i = 0; i < 4; i++)
#pragma unroll
        for (int j = 0; j < 8; j++) acc[i][j] = 0ull;

    const float* midb = g_mid + (size_t)b * HW * NMID;

    for (int k0 = 0; k0 < NMID; k0 += 16) {
        {
            int m = tid >> 2, kq = (tid & 3) * 4;
            float4 v = *(const float4*)(midb + (size_t)(p0 + m) * NMID + k0 + kq);
            As[(kq + 0) * 66 + m] = v.x;
            As[(kq + 1) * 66 + m] = v.y;
            As[(kq + 2) * 66 + m] = v.z;
            As[(kq + 3) * 66 + m] = v.w;
        }
#pragma unroll
        for (int r = 0; r < 16; r++) {
            int idx = tid + 256 * r;
            int kk = idx >> 8, n = idx & 255;
            Bs[kk * 256 + n] = g_pT[(k0 + kk) * DIMC + n];
        }
        __syncthreads();
#pragma unroll
        for (int kk = 0; kk < 16; kk++) {
            const u64t* Ap = (const u64t*)(As + kk * 66);
            u64t a2[4], b2[8];
#pragma unroll
            for (int i = 0; i < 4; i++) a2[i] = Ap[8 * i + tm];
#pragma unroll
            for (int j = 0; j < 8; j++) {
                float bv = Bs[kk * 256 + tn + 32 * j];
                b2[j] = pk2(bv, bv);
            }
#pragma unroll
            for (int i = 0; i < 4; i++)
#pragma unroll
                for (int j = 0; j < 8; j++) ffma2(acc[i][j], a2[i], b2[j]);
        }
        __syncthreads();
    }

    // epilogue in two 128-channel halves through padded smem (pitch 65)
    for (int half = 0; half < 2; half++) {
        __syncthreads();
#pragma unroll
        for (int jj = 0; jj < 4; jj++) {
            int j = half * 4 + jj;
            int n = tn + 32 * j;
            float bias = proj_b[n];
            int row = n - half * 128;
#pragma unroll
            for (int i = 0; i < 4; i++) {
                float2 v = upk2(acc[i][j]);
                int m = 16 * i + 2 * tm;
                sbuf[row * 65 + m]     = v.x + bias;
                sbuf[row * 65 + m + 1] = v.y + bias;
            }
        }
        __syncthreads();
#pragma unroll
        for (int r = 0; r < 32; r++) {
            int idx = tid + 256 * r;
            int n = idx >> 6, m = idx & 63;
            out[((size_t)b * DIMC + half * 128 + n) * HW + p0 + m] = sbuf[n * 65 + m];
        }
    }
}

// ---------------------------------------------------------------------------
extern "C" void kernel_launch(void* const* d_in, const int* in_sizes, int n_in,
                              void* d_out, int out_size) {
    const float* x      = (const float*)d_in[0];
    const float* qkv_w  = (const float*)d_in[1];
    const float* qkv_b  = (const float*)d_in[2];
    const float* dc_b   = (const float*)d_in[3];
    const float* dc1_w  = (const float*)d_in[4];
    const float* dc1_b  = (const float*)d_in[5];
    const float* rpb    = (const float*)d_in[6];
    const float* proj_w = (const float*)d_in[7];
    const float* proj_b = (const float*)d_in[8];
    float* out = (float*)d_out;

    k_prep<<<64, 256>>>(qkv_w, proj_w);
    k_qkv<<<dim3(49, NB), 256>>>(x, qkv_b);
    k_attn_a<<<dim3(14, 8, NB), 224>>>(dc_b, dc1_w, dc1_b, rpb);
    k_attn_b<<<dim3(14, 8, NB), 224>>>(dc_b, dc1_w, dc1_b);
    k_proj<<<dim3(49, NB), 256>>>(proj_b, out);
    (void)in_sizes; (void)n_in; (void)out_size;
}

// round 9
// speedup vs baseline: 3.7020x; 1.0012x over previous
#include <cuda_runtime.h>

#define NB   16
#define HH   56
#define HW   3136
#define DIMC 256
#define NQKV 192
#define NMID 64
#define SCALE_F 0.17677669529663688f

typedef unsigned long long u64t;

// packed f32x2 helpers (SASS FFMA2 — only reachable via PTX fma.rn.f32x2)
__device__ __forceinline__ u64t pk2(float lo, float hi) {
    u64t r; asm("mov.b64 %0, {%1, %2};" : "=l"(r) : "f"(lo), "f"(hi)); return r;
}
__device__ __forceinline__ float2 upk2(u64t v) {
    float2 f; asm("mov.b64 {%0, %1}, %2;" : "=f"(f.x), "=f"(f.y) : "l"(v)); return f;
}
__device__ __forceinline__ void ffma2(u64t& d, u64t a, u64t b) {
    asm("fma.rn.f32x2 %0, %1, %2, %0;" : "+l"(d) : "l"(a), "l"(b));
}

// Scratch (static __device__ arrays — allocation-free per harness rules)
static __device__ float g_f[NB * HW * NQKV];        // [b][pixel][192] pixel-major
static __device__ float g_mid[NB * HW * NMID];      // [b][pixel][64]  pixel-major
static __device__ float g_attn[NB * 8 * 9 * HW];    // [b][h][idx][pixel] plane-major
static __device__ float g_wT[DIMC * NQKV];          // qkv_w transposed [k][n]
static __device__ float g_pT[NMID * DIMC];          // proj_w transposed [k][n]

// ---------------------------------------------------------------------------
// Kernel 0: transpose weights once (tiny)
// ---------------------------------------------------------------------------
__global__ void k_prep(const float* __restrict__ qkv_w,
                       const float* __restrict__ proj_w) {
    int stride = gridDim.x * blockDim.x;
    int i0 = blockIdx.x * blockDim.x + threadIdx.x;
    for (int i = i0; i < DIMC * NQKV; i += stride) {
        int k = i / NQKV, n = i - k * NQKV;
        g_wT[i] = qkv_w[n * DIMC + k];
    }
    for (int i = i0; i < NMID * DIMC; i += stride) {
        int k = i / DIMC, n = i - k * DIMC;
        g_pT[i] = proj_w[n * NMID + k];
    }
}

// ---------------------------------------------------------------------------
// Kernel 1: QKV GEMM.  C[p][n] = sum_k x[b][k][p] * qkv_w[n][k] + qkv_b[n]
// Tile: 64 pixels x 192 outputs, BK=16.  256 threads, f32x2 packed FMAs.
// v2: duplicated-B smem (kills per-kk mov splats) + global prefetch pipeline.
// ---------------------------------------------------------------------------
__global__ __launch_bounds__(256) void k_qkv(const float* __restrict__ x,
                                             const float* __restrict__ qkv_b) {
    __shared__ __align__(16) float As[16 * 64];
    __shared__ __align__(16) u64t  Bs2[16 * 192];   // (b,b) duplicated pairs
    const int tid = threadIdx.x;
    const int b   = blockIdx.y;
    const int p0  = blockIdx.x * 64;
    const int tn  = tid & 31;   // n lane
    const int tm  = tid >> 5;   // m group (uniform per warp)

    u64t acc[4][6];
#pragma unroll
    for (int i = 0; i < 4; i++)
#pragma unroll
        for (int j = 0; j < 6; j++) acc[i][j] = 0ull;

    const float* xb = x + (size_t)b * DIMC * HW;

    // prefetch registers for the software pipeline
    float xa[4], wb[12];
    // loader index precompute
    int a_kk[4], a_m[4], b_kk[12], b_n[12];
#pragma unroll
    for (int r = 0; r < 4; r++) {
        int idx = tid + 256 * r;
        a_kk[r] = idx >> 6; a_m[r] = idx & 63;
    }
#pragma unroll
    for (int r = 0; r < 12; r++) {
        int idx = tid + 256 * r;
        b_kk[r] = idx / 192; b_n[r] = idx - b_kk[r] * 192;
    }

    // load tile 0
#pragma unroll
    for (int r = 0; r < 4; r++)
        xa[r] = xb[(size_t)a_kk[r] * HW + p0 + a_m[r]];
#pragma unroll
    for (int r = 0; r < 12; r++)
        wb[r] = g_wT[b_kk[r] * NQKV + b_n[r]];

    for (int k0 = 0; k0 < DIMC; k0 += 16) {
        // commit prefetched tile to smem
#pragma unroll
        for (int r = 0; r < 4; r++) As[a_kk[r] * 64 + a_m[r]] = xa[r];
#pragma unroll
        for (int r = 0; r < 12; r++) Bs2[b_kk[r] * 192 + b_n[r]] = pk2(wb[r], wb[r]);
        __syncthreads();

        // prefetch next tile (overlaps with compute below)
        if (k0 + 16 < DIMC) {
#pragma unroll
            for (int r = 0; r < 4; r++)
                xa[r] = xb[(size_t)(k0 + 16 + a_kk[r]) * HW + p0 + a_m[r]];
#pragma unroll
            for (int r = 0; r < 12; r++)
                wb[r] = g_wT[(k0 + 16 + b_kk[r]) * NQKV + b_n[r]];
        }

#pragma unroll
        for (int kk = 0; kk < 16; kk++) {
            const u64t* Ap = (const u64t*)(As + kk * 64);
            const u64t* Bp = Bs2 + kk * 192;
            u64t a2[4], b2[6];
#pragma unroll
            for (int i = 0; i < 4; i++) a2[i] = Ap[8 * i + tm];
#pragma unroll
            for (int j = 0; j < 6; j++) b2[j] = Bp[tn + 32 * j];
#pragma unroll
            for (int i = 0; i < 4; i++)
#pragma unroll
                for (int j = 0; j < 6; j++) ffma2(acc[i][j], a2[i], b2[j]);
        }
        __syncthreads();
    }

#pragma unroll
    for (int j = 0; j < 6; j++) {
        int n = tn + 32 * j;
        float bias = qkv_b[n];
#pragma unroll
        for (int i = 0; i < 4; i++) {
            float2 v = upk2(acc[i][j]);
            size_t row = (size_t)b * HW + p0 + 16 * i + 2 * tm;
            g_f[row * NQKV + n]       = v.x + bias;
            g_f[(row + 1) * NQKV + n] = v.y + bias;
        }
    }
}

// ---------------------------------------------------------------------------
// Kernel 2a: K branch + softmax.  Channel-quad (float4 / LDS.128) version.
// One thread per (pixel, head); block = 56x4 strip for one (b,h).
// ---------------------------------------------------------------------------
__global__ __launch_bounds__(224, 3) void k_attn_a(const float* __restrict__ dc_b,
                                                   const float* __restrict__ dc1_w,
                                                   const float* __restrict__ dc1_b,
                                                   const float* __restrict__ rpb) {
    __shared__ __align__(16) float4 sk4[2][6][58];   // [cq][y][x], channels 4cq..4cq+3
    __shared__ __align__(16) float4 wp4[2][81];      // [cq][idx*9+t]
    __shared__ __align__(16) float4 bias4[2][9];     // [cq][idx]
    __shared__ float srpb[9];

    const int tid  = threadIdx.x;
    const int tile = blockIdx.x;   // 0..13  (rows y0..y0+3)
    const int h    = blockIdx.y;
    const int b    = blockIdx.z;
    const int y0   = tile * 4;

    // wp4 fill: i = c*81 + idx*9 + t == dc1_w flat index
    {
        float* wp4f = (float*)wp4;
        for (int i = tid; i < 648; i += 224) {
            int c = i / 81, r = i - c * 81;
            int idx = r / 9, t = r - idx * 9;
            float v = dc1_w[i] + ((t == idx) ? 1.0f : 0.0f);
            wp4f[((c >> 2) * 81 + r) * 4 + (c & 3)] = v;
        }
        float* bias4f = (float*)bias4;
        for (int i = tid; i < 72; i += 224) {
            int c = i / 9, idx = i - c * 9;
            bias4f[((c >> 2) * 9 + idx) * 4 + (c & 3)] = dc_b[i] + dc1_b[i];
        }
        if (tid < 9) srpb[tid] = rpb[h * 9 + tid];
    }

    const float* fb = g_f + (size_t)b * HW * NQKV + h * 24;

    // halo tile (K channels): 6 rows x 58 cols, zero padded
    for (int i = tid; i < 348; i += 224) {
        int hy = i / 58, hx = i - hy * 58;
        int gy = y0 + hy - 1, gx = hx - 1;
        float4 a0, a1;
        if (gy >= 0 && gy < HH && gx >= 0 && gx < HH) {
            const float* pf = fb + (size_t)(gy * HH + gx) * NQKV;
            a0 = *(const float4*)(pf + 8);
            a1 = *(const float4*)(pf + 12);
        } else {
            a0 = a1 = make_float4(0.f, 0.f, 0.f, 0.f);
        }
        sk4[0][hy][hx] = a0;
        sk4[1][hy][hx] = a1;
    }
    __syncthreads();

    const int ty = tid / 56, tx = tid - ty * 56;
    const int p  = (y0 + ty) * HH + tx;
    const float* pf = fb + (size_t)p * NQKV;
    float4 q0 = *(const float4*)pf;
    float4 q1 = *(const float4*)(pf + 4);
    // packed q pairs: q2[cq][half]
    u64t q2[2][2];
    q2[0][0] = pk2(q0.x * SCALE_F, q0.y * SCALE_F);
    q2[0][1] = pk2(q0.z * SCALE_F, q0.w * SCALE_F);
    q2[1][0] = pk2(q1.x * SCALE_F, q1.y * SCALE_F);
    q2[1][1] = pk2(q1.z * SCALE_F, q1.w * SCALE_F);
    float qsum = (q0.x + q0.y + q0.z + q0.w + q1.x + q1.y + q1.z + q1.w) * SCALE_F;

    u64t logit2[9];
#pragma unroll
    for (int i = 0; i < 9; i++) logit2[i] = 0ull;

#pragma unroll
    for (int cq = 0; cq < 2; cq++) {
        ulonglong2 nb2[9];
#pragma unroll
        for (int dy = 0; dy < 3; dy++)
#pragma unroll
            for (int dx = 0; dx < 3; dx++)
                nb2[dy * 3 + dx] = *(const ulonglong2*)&sk4[cq][ty + dy][tx + dx];
        const ulonglong2* wq = (const ulonglong2*)wp4[cq];
        const ulonglong2* bq = (const ulonglong2*)bias4[cq];
        u64t qlo = q2[cq][0], qhi = q2[cq][1];
#pragma unroll
        for (int idx = 0; idx < 9; idx++) {
            ulonglong2 av = bq[idx];
#pragma unroll
            for (int t = 0; t < 9; t++) {
                ulonglong2 wv = wq[idx * 9 + t];
                ffma2(av.x, nb2[t].x, wv.x);
                ffma2(av.y, nb2[t].y, wv.y);
            }
            ffma2(logit2[idx], qlo, av.x);
            ffma2(logit2[idx], qhi, av.y);
        }
    }

    float logit[9];
#pragma unroll
    for (int idx = 0; idx < 9; idx++) {
        float2 l2 = upk2(logit2[idx]);
        logit[idx] = l2.x + l2.y + qsum * srpb[idx];
    }

    // softmax over 9 taps
    float mx = logit[0];
#pragma unroll
    for (int idx = 1; idx < 9; idx++) mx = fmaxf(mx, logit[idx]);
    float s = 0.f;
#pragma unroll
    for (int idx = 0; idx < 9; idx++) {
        logit[idx] = __expf(logit[idx] - mx);
        s += logit[idx];
    }
    float inv = 1.0f / s;

    float* pa = g_attn + (((size_t)b * 8 + h) * 9) * HW + p;
#pragma unroll
    for (int idx = 0; idx < 9; idx++)
        pa[(size_t)idx * HW] = logit[idx] * inv;     // coalesced per idx-plane
}

// ---------------------------------------------------------------------------
// Kernel 2b: V branch, channel-quad version.  attn planes -> g_mid.
// ---------------------------------------------------------------------------
__global__ __launch_bounds__(224, 3) void k_attn_b(const float* __restrict__ dc_b,
                                                   const float* __restrict__ dc1_w,
                                                   const float* __restrict__ dc1_b) {
    __shared__ __align__(16) float4 sv4[2][6][58];
    __shared__ __align__(16) float4 wp4[2][81];
    __shared__ __align__(16) float4 bias4[2][9];

    const int tid  = threadIdx.x;
    const int tile = blockIdx.x;
    const int h    = blockIdx.y;
    const int b    = blockIdx.z;
    const int y0   = tile * 4;

    {
        float* wp4f = (float*)wp4;
        for (int i = tid; i < 648; i += 224) {
            int c = i / 81, r = i - c * 81;
            int idx = r / 9, t = r - idx * 9;
            float v = dc1_w[i] + ((t == idx) ? 1.0f : 0.0f);
            wp4f[((c >> 2) * 81 + r) * 4 + (c & 3)] = v;
        }
        float* bias4f = (float*)bias4;
        for (int i = tid; i < 72; i += 224) {
            int c = i / 9, idx = i - c * 9;
            bias4f[((c >> 2) * 9 + idx) * 4 + (c & 3)] = dc_b[i] + dc1_b[i];
        }
    }

    const float* fb = g_f + (size_t)b * HW * NQKV + h * 24;

    // halo tile (V channels)
    for (int i = tid; i < 348; i += 224) {
        int hy = i / 58, hx = i - hy * 58;
        int gy = y0 + hy - 1, gx = hx - 1;
        float4 c0, c1;
        if (gy >= 0 && gy < HH && gx >= 0 && gx < HH) {
            const float* pf = fb + (size_t)(gy * HH + gx) * NQKV;
            c0 = *(const float4*)(pf + 16);
            c1 = *(const float4*)(pf + 20);
        } else {
            c0 = c1 = make_float4(0.f, 0.f, 0.f, 0.f);
        }
        sv4[0][hy][hx] = c0;
        sv4[1][hy][hx] = c1;
    }
    __syncthreads();

    const int ty = tid / 56, tx = tid - ty * 56;
    const int p  = (y0 + ty) * HH + tx;

    u64t attn2[9];
    const float* pa = g_attn + (((size_t)b * 8 + h) * 9) * HW + p;
#pragma unroll
    for (int idx = 0; idx < 9; idx++) {
        float a = pa[(size_t)idx * HW];
        attn2[idx] = pk2(a, a);
    }

    float* po = g_mid + ((size_t)b * HW + p) * NMID + h * 8;

#pragma unroll
    for (int cq = 0; cq < 2; cq++) {
        ulonglong2 nb2[9];
#pragma unroll
        for (int dy = 0; dy < 3; dy++)
#pragma unroll
            for (int dx = 0; dx < 3; dx++)
                nb2[dy * 3 + dx] = *(const ulonglong2*)&sv4[cq][ty + dy][tx + dx];
        const ulonglong2* wq = (const ulonglong2*)wp4[cq];
        const ulonglong2* bq = (const ulonglong2*)bias4[cq];
        u64t olo = 0ull, ohi = 0ull;
#pragma unroll
        for (int idx = 0; idx < 9; idx++) {
            ulonglong2 av = bq[idx];
#pragma unroll
            for (int t = 0; t < 9; t++) {
                ulonglong2 wv = wq[idx * 9 + t];
                ffma2(av.x, nb2[t].x, wv.x);
                ffma2(av.y, nb2[t].y, wv.y);
            }
            ffma2(olo, attn2[idx], av.x);
            ffma2(ohi, attn2[idx], av.y);
        }
        float2 o0 = upk2(olo), o1 = upk2(ohi);
        *(float4*)(po + cq * 4) = make_float4(o0.x, o0.y, o1.x, o1.y);
    }
}

// ---------------------------------------------------------------------------
// Kernel 3: proj GEMM.  out[b][n][p] = sum_k mid[b][p][k]*proj_w[n][k]+proj_b[n]
// Tile: 64 pixels x 256 outputs, BK=16.  256 threads, f32x2 packed FMAs.
// Epilogue transposes through padded smem for coalesced NCHW writes.
// ---------------------------------------------------------------------------
__global__ __launch_bounds__(256) void k_proj(const float* __restrict__ proj_b,
                                              float* __restrict__ out) {
    __shared__ __align__(16) float sbuf[128 * 65];  // unions mainloop + epilogue
    float* As = sbuf;                 // mainloop: pitch 66 (even, 8B-pair safe)
    float* Bs = sbuf + 16 * 66;       // 16 x 256
    const int tid = threadIdx.x;
    const int b   = blockIdx.y;
    const int p0  = blockIdx.x * 64;
    const int tn  = tid & 31;
    const int tm  = tid >> 5;

    u64t acc[4][8];
#pragma unroll
    for (int i = 0; i < 4; i++)
#pragma unroll
        for (int j = 0; j < 8; j++) acc[i][j] = 0ull;

    const float* midb = g_mid + (size_t)b * HW * NMID;

    for (int k0 = 0; k0 < NMID; k0 += 16) {
        {
            int m = tid >> 2, kq = (tid & 3) * 4;
            float4 v = *(const float4*)(midb + (size_t)(p0 + m) * NMID + k0 + kq);
            As[(kq + 0) * 66 + m] = v.x;
            As[(kq + 1) * 66 + m] = v.y;
            As[(kq + 2) * 66 + m] = v.z;
            As[(kq + 3) * 66 + m] = v.w;
        }
#pragma unroll
        for (int r = 0; r < 16; r++) {
            int idx = tid + 256 * r;
            int kk = idx >> 8, n = idx & 255;
            Bs[kk * 256 + n] = g_pT[(k0 + kk) * DIMC + n];
        }
        __syncthreads();
#pragma unroll
        for (int kk = 0; kk < 16; kk++) {
            const u64t* Ap = (const u64t*)(As + kk * 66);
            u64t a2[4], b2[8];
#pragma unroll
            for (int i = 0; i < 4; i++) a2[i] = Ap[8 * i + tm];
#pragma unroll
            for (int j = 0; j < 8; j++) {
                float bv = Bs[kk * 256 + tn + 32 * j];
                b2[j] = pk2(bv, bv);
            }
#pragma unroll
            for (int i = 0; i < 4; i++)
#pragma unroll
                for (int j = 0; j < 8; j++) ffma2(acc[i][j], a2[i], b2[j]);
        }
        __syncthreads();
    }

    // epilogue in two 128-channel halves through padded smem (pitch 65)
    for (int half = 0; half < 2; half++) {
        __syncthreads();
#pragma unroll
        for (int jj = 0; jj < 4; jj++) {
            int j = half * 4 + jj;
            int n = tn + 32 * j;
            float bias = proj_b[n];
            int row = n - half * 128;
#pragma unroll
            for (int i = 0; i < 4; i++) {
                float2 v = upk2(acc[i][j]);
                int m = 16 * i + 2 * tm;
                sbuf[row * 65 + m]     = v.x + bias;
                sbuf[row * 65 + m + 1] = v.y + bias;
            }
        }
        __syncthreads();
#pragma unroll
        for (int r = 0; r < 32; r++) {
            int idx = tid + 256 * r;
            int n = idx >> 6, m = idx & 63;
            out[((size_t)b * DIMC + half * 128 + n) * HW + p0 + m] = sbuf[n * 65 + m];
        }
    }
}

// ---------------------------------------------------------------------------
extern "C" void kernel_launch(void* const* d_in, const int* in_sizes, int n_in,
                              void* d_out, int out_size) {
    const float* x      = (const float*)d_in[0];
    const float* qkv_w  = (const float*)d_in[1];
    const float* qkv_b  = (const float*)d_in[2];
    const float* dc_b   = (const float*)d_in[3];
    const float* dc1_w  = (const float*)d_in[4];
    const float* dc1_b  = (const float*)d_in[5];
    const float* rpb    = (const float*)d_in[6];
    const float* proj_w = (const float*)d_in[7];
    const float* proj_b = (const float*)d_in[8];
    float* out = (float*)d_out;

    k_prep<<<64, 256>>>(qkv_w, proj_w);
    k_qkv<<<dim3(49, NB), 256>>>(x, qkv_b);
    k_attn_a<<<dim3(14, 8, NB), 224>>>(dc_b, dc1_w, dc1_b, rpb);
    k_attn_b<<<dim3(14, 8, NB), 224>>>(dc_b, dc1_w, dc1_b);
    k_proj<<<dim3(49, NB), 256>>>(proj_b, out);
    (void)in_sizes; (void)n_in; (void)out_size;
}